// round 8
// baseline (speedup 1.0000x reference)
#include <cuda_runtime.h>
#include <math.h>

// signal (32, 1024, 2) f32 interleaved. Per (batch, channel):
//   anded[t] = -|s| - log1p(exp(-2e5|s|))/1e5
//   out[t]   = suffix max of anded  (EV_SCALE=1e9 maxish == hard max to ~1e-9)
//
// ONE WARP PER BATCH: grid=32, block=32, zero smem, zero barriers.
// Thread t owns timesteps [32t, 32t+32): 16x LDG.128 (MLP=16), serial
// in-register suffix max (31 dependent fmax x 2 channels, interleaved ILP),
// then one 5-stage shfl suffix scan + shfl carry. Warp-uniform MUFU fast
// path: corr==0 exactly when |c| > 4.37e-4 (expf underflow).

static constexpr int T = 1024;
static constexpr int B = 32;
static constexpr int EPT = 32;           // timesteps per thread

__device__ __forceinline__ float corr_of(float a) {
    return __logf(1.0f + __expf(-200000.0f * a)) * 1e-5f;
}

__global__ __launch_bounds__(32)
void suffix_robustness_kernel(const float4* __restrict__ signal,
                              float4* __restrict__ out) {
    const int b    = blockIdx.x;
    const int t    = threadIdx.x;        // lane == thread
    const int lane = t;

    // Row b: 2048 floats = 512 float4. Thread t reads float4 [16t, 16t+16).
    const float4* row = signal + b * (T * 2 / 4) + t * 16;

    float4 v[16];
    #pragma unroll
    for (int i = 0; i < 16; i++) v[i] = row[i];   // 16 outstanding LDG.128

    float ax[EPT], ay[EPT];
    float amin = INFINITY;
    #pragma unroll
    for (int i = 0; i < 16; i++) {
        ax[2 * i]     = fabsf(v[i].x);  ay[2 * i]     = fabsf(v[i].y);
        ax[2 * i + 1] = fabsf(v[i].z);  ay[2 * i + 1] = fabsf(v[i].w);
        amin = fminf(amin, fminf(fminf(ax[2 * i], ay[2 * i]),
                                 fminf(ax[2 * i + 1], ay[2 * i + 1])));
    }

    if (__ballot_sync(0xffffffffu, amin < 4.5e-4f)) {
        #pragma unroll
        for (int i = 0; i < EPT; i++) {
            ax[i] = -ax[i] - corr_of(ax[i]);
            ay[i] = -ay[i] - corr_of(ay[i]);
        }
    } else {
        #pragma unroll
        for (int i = 0; i < EPT; i++) { ax[i] = -ax[i]; ay[i] = -ay[i]; }
    }

    // Serial in-register suffix max: a[i] = max(a[i..EPT-1]).
    // Two independent chains (x,y) interleave on the FMA pipe.
    #pragma unroll
    for (int i = EPT - 2; i >= 0; i--) {
        ax[i] = fmaxf(ax[i], ax[i + 1]);
        ay[i] = fmaxf(ay[i], ay[i + 1]);
    }

    // Warp suffix-inclusive scan of thread totals (ax[0]/ay[0]).
    float sx = ax[0], sy = ay[0];
    #pragma unroll
    for (int off = 1; off < 32; off <<= 1) {
        float ox = __shfl_down_sync(0xffffffffu, sx, off);
        float oy = __shfl_down_sync(0xffffffffu, sy, off);
        sx = fmaxf(sx, ox);
        sy = fmaxf(sy, oy);
    }
    // Carry from later threads = scan value at lane+1 (lane 31 -> -inf).
    float cx = __shfl_down_sync(0xffffffffu, sx, 1);
    float cy = __shfl_down_sync(0xffffffffu, sy, 1);
    if (lane == 31) { cx = -INFINITY; cy = -INFINITY; }

    // Apply carry and store. Output: (final, final_2) concatenated, each
    // (32,1024) row-major => row b is 256 float4; thread t writes [8t, 8t+8).
    float4* ox_out = out + b * (T / 4) + t * 8;
    float4* oy_out = out + B * (T / 4) + b * (T / 4) + t * 8;
    #pragma unroll
    for (int q = 0; q < 8; q++) {
        float4 o;
        o.x = fmaxf(ax[4 * q + 0], cx);
        o.y = fmaxf(ax[4 * q + 1], cx);
        o.z = fmaxf(ax[4 * q + 2], cx);
        o.w = fmaxf(ax[4 * q + 3], cx);
        ox_out[q] = o;
    }
    #pragma unroll
    for (int q = 0; q < 8; q++) {
        float4 o;
        o.x = fmaxf(ay[4 * q + 0], cy);
        o.y = fmaxf(ay[4 * q + 1], cy);
        o.z = fmaxf(ay[4 * q + 2], cy);
        o.w = fmaxf(ay[4 * q + 3], cy);
        oy_out[q] = o;
    }
}

extern "C" void kernel_launch(void* const* d_in, const int* in_sizes, int n_in,
                              void* d_out, int out_size) {
    const float4* signal = (const float4*)d_in[0];
    float4* out = (float4*)d_out;
    suffix_robustness_kernel<<<B, 32>>>(signal, out);
}

// round 9
// speedup vs baseline: 1.4115x; 1.4115x over previous
#include <cuda_runtime.h>
#include <math.h>

// signal (32, 1024, 2) f32 interleaved. Per (batch, channel):
//   anded[t] = -|s| - log1p(exp(-2e5|s|))/1e5
//   out[t]   = suffix max of anded  (EV_SCALE=1e9 maxish == hard max to ~1e-9)
//
// grid=32 (one CTA per batch), 256 threads, 4 timesteps/thread (best-measured
// R6 shape). Warp-uniform MUFU fast path (corr==0 exactly when |c|>4.37e-4).
// Scan: 3 serial fmax -> 5-shfl warp suffix scan -> 1 barrier (8 warps)
//       -> padded smem carry: totals[16] with [8..15]=-INF so the 7-successor
//          combine is a predicate-free 3-level tree over pipelined LDS loads.

static constexpr int T = 1024;
static constexpr int B = 32;
static constexpr int THREADS = 256;
static constexpr int NWARP = THREADS / 32;

__device__ __forceinline__ float corr_of(float a) {
    return __logf(1.0f + __expf(-200000.0f * a)) * 1e-5f;
}

__global__ __launch_bounds__(THREADS)
void suffix_robustness_kernel(const float4* __restrict__ signal,
                              float4* __restrict__ out) {
    __shared__ float totx[2 * NWARP];
    __shared__ float toty[2 * NWARP];

    const int b    = blockIdx.x;
    const int t    = threadIdx.x;        // thread handles timesteps 4t..4t+3
    const int lane = t & 31;
    const int wid  = t >> 5;

    // Pad entries [NWARP, 2*NWARP) with -INF (covered by the barrier below).
    if (t >= NWARP && t < 2 * NWARP) { totx[t] = -INFINITY; toty[t] = -INFINITY; }

    // signal row b: 2048 floats = 512 float4. Thread t takes float4 idx 2t, 2t+1.
    const float4* row = signal + b * (T * 2 / 4);
    float4 p0 = row[2 * t];              // ts 4t:   (x0,y0,x1,y1)
    float4 p1 = row[2 * t + 1];          // ts 4t+2: (x2,y2,x3,y3)

    float ax0 = fabsf(p0.x), ay0 = fabsf(p0.y);
    float ax1 = fabsf(p0.z), ay1 = fabsf(p0.w);
    float ax2 = fabsf(p1.x), ay2 = fabsf(p1.y);
    float ax3 = fabsf(p1.z), ay3 = fabsf(p1.w);

    float amin = fminf(fminf(fminf(ax0, ay0), fminf(ax1, ay1)),
                       fminf(fminf(ax2, ay2), fminf(ax3, ay3)));

    // anded = -|c| - corr;  corr==0 exactly when |c| > 4.37e-4.
    if (__ballot_sync(0xffffffffu, amin < 4.5e-4f)) {
        ax0 = -ax0 - corr_of(ax0);  ay0 = -ay0 - corr_of(ay0);
        ax1 = -ax1 - corr_of(ax1);  ay1 = -ay1 - corr_of(ay1);
        ax2 = -ax2 - corr_of(ax2);  ay2 = -ay2 - corr_of(ay2);
        ax3 = -ax3 - corr_of(ax3);  ay3 = -ay3 - corr_of(ay3);
    } else {
        ax0 = -ax0;  ay0 = -ay0;
        ax1 = -ax1;  ay1 = -ay1;
        ax2 = -ax2;  ay2 = -ay2;
        ax3 = -ax3;  ay3 = -ay3;
    }

    // Per-thread suffix max: a_i = max(a_i .. a_3)
    ax2 = fmaxf(ax2, ax3);  ay2 = fmaxf(ay2, ay3);
    ax1 = fmaxf(ax1, ax2);  ay1 = fmaxf(ay1, ay2);
    ax0 = fmaxf(ax0, ax1);  ay0 = fmaxf(ay0, ay1);

    // Warp suffix-inclusive scan of thread totals (ax0/ay0).
    float sx = ax0, sy = ay0;
    #pragma unroll
    for (int off = 1; off < 32; off <<= 1) {
        float ox = __shfl_down_sync(0xffffffffu, sx, off);
        float oy = __shfl_down_sync(0xffffffffu, sy, off);
        sx = fmaxf(sx, ox);
        sy = fmaxf(sy, oy);
    }
    // Carry from later threads in this warp = scan value at lane+1.
    float cx = __shfl_down_sync(0xffffffffu, sx, 1);
    float cy = __shfl_down_sync(0xffffffffu, sy, 1);
    if (lane == 31) { cx = -INFINITY; cy = -INFINITY; }

    // Publish warp totals (scan value at lane 0).
    if (lane == 0) { totx[wid] = sx; toty[wid] = sy; }

    // Hoist store bases off the post-barrier critical path.
    float4* ox_out = out + b * (T / 4) + t;
    float4* oy_out = out + B * (T / 4) + b * (T / 4) + t;

    __syncthreads();

    // Predicate-free carry from later warps: 7 pipelined broadcast LDS loads
    // (padding supplies -INF past warp 7), then a 3-level tree max.
    {
        float x1 = totx[wid + 1], x2 = totx[wid + 2], x3 = totx[wid + 3],
              x4 = totx[wid + 4], x5 = totx[wid + 5], x6 = totx[wid + 6],
              x7 = totx[wid + 7];
        float y1 = toty[wid + 1], y2 = toty[wid + 2], y3 = toty[wid + 3],
              y4 = toty[wid + 4], y5 = toty[wid + 5], y6 = toty[wid + 6],
              y7 = toty[wid + 7];
        float xa = fmaxf(x1, x2), xb = fmaxf(x3, x4), xc = fmaxf(x5, x6);
        float ya = fmaxf(y1, y2), yb = fmaxf(y3, y4), yc = fmaxf(y5, y6);
        cx = fmaxf(cx, fmaxf(fmaxf(xa, xb), fmaxf(xc, x7)));
        cy = fmaxf(cy, fmaxf(fmaxf(ya, yb), fmaxf(yc, y7)));
    }

    float4 ox4, oy4;
    ox4.x = fmaxf(ax0, cx);  oy4.x = fmaxf(ay0, cy);
    ox4.y = fmaxf(ax1, cx);  oy4.y = fmaxf(ay1, cy);
    ox4.z = fmaxf(ax2, cx);  oy4.z = fmaxf(ay2, cy);
    ox4.w = fmaxf(ax3, cx);  oy4.w = fmaxf(ay3, cy);

    // Outputs: (final, final_2) concatenated, each (32,1024) row-major.
    *ox_out = ox4;
    *oy_out = oy4;
}

extern "C" void kernel_launch(void* const* d_in, const int* in_sizes, int n_in,
                              void* d_out, int out_size) {
    const float4* signal = (const float4*)d_in[0];
    float4* out = (float4*)d_out;
    suffix_robustness_kernel<<<B, THREADS>>>(signal, out);
}

// round 11
// speedup vs baseline: 1.4415x; 1.0213x over previous
#include <cuda_runtime.h>
#include <math.h>

// signal (32, 1024, 2) f32 interleaved. Per (batch, channel):
//   anded[t] = -|s| - log1p(exp(-2e5|s|))/1e5
//   out[t]   = suffix max of anded  (EV_SCALE=1e9 maxish == hard max to ~1e-9)
//
// grid=64: one CTA per (batch, channel). 128 threads, 8 timesteps/thread
// (4x LDG.128), 4 warps. Single-channel scan chain, 4-warp barrier,
// 3-load predicate-free padded smem carry. Warp-uniform MUFU fast path
// (corr==0 exactly when |c| > 4.37e-4, expf underflow).

static constexpr int T = 1024;
static constexpr int B = 32;
static constexpr int THREADS = 128;
static constexpr int NWARP = THREADS / 32;   // 4

__device__ __forceinline__ float corr_of(float a) {
    return __logf(1.0f + __expf(-200000.0f * a)) * 1e-5f;
}

__global__ __launch_bounds__(THREADS)
void suffix_robustness_kernel(const float4* __restrict__ signal,
                              float* __restrict__ out) {
    __shared__ float tot[2 * NWARP];

    const int b    = blockIdx.x;         // batch
    const int ch   = blockIdx.y;         // channel 0/1
    const int t    = threadIdx.x;        // thread handles timesteps 8t..8t+7
    const int lane = t & 31;
    const int wid  = t >> 5;

    // Pad totals [NWARP, 2*NWARP) with -INF (covered by the barrier below).
    if (t >= NWARP && t < 2 * NWARP) tot[t] = -INFINITY;

    // signal row b: 2048 floats = 512 float4. Each float4 = 2 timesteps of
    // both channels. Thread t reads float4 indices 4t..4t+3 (ts 8t..8t+7).
    const float4* row = signal + b * (T * 2 / 4) + 4 * t;
    float4 p0 = row[0];
    float4 p1 = row[1];
    float4 p2 = row[2];
    float4 p3 = row[3];

    float a0 = fabsf(ch ? p0.y : p0.x);
    float a1 = fabsf(ch ? p0.w : p0.z);
    float a2 = fabsf(ch ? p1.y : p1.x);
    float a3 = fabsf(ch ? p1.w : p1.z);
    float a4 = fabsf(ch ? p2.y : p2.x);
    float a5 = fabsf(ch ? p2.w : p2.z);
    float a6 = fabsf(ch ? p3.y : p3.x);
    float a7 = fabsf(ch ? p3.w : p3.z);

    float amin = fminf(fminf(fminf(a0, a1), fminf(a2, a3)),
                       fminf(fminf(a4, a5), fminf(a6, a7)));

    // anded = -|c| - corr;  corr==0 exactly when |c| > 4.37e-4.
    if (__ballot_sync(0xffffffffu, amin < 4.5e-4f)) {
        a0 = -a0 - corr_of(a0);  a1 = -a1 - corr_of(a1);
        a2 = -a2 - corr_of(a2);  a3 = -a3 - corr_of(a3);
        a4 = -a4 - corr_of(a4);  a5 = -a5 - corr_of(a5);
        a6 = -a6 - corr_of(a6);  a7 = -a7 - corr_of(a7);
    } else {
        a0 = -a0;  a1 = -a1;  a2 = -a2;  a3 = -a3;
        a4 = -a4;  a5 = -a5;  a6 = -a6;  a7 = -a7;
    }

    // Per-thread suffix max: a_i = max(a_i .. a_7)
    a6 = fmaxf(a6, a7);
    a5 = fmaxf(a5, a6);
    a4 = fmaxf(a4, a5);
    a3 = fmaxf(a3, a4);
    a2 = fmaxf(a2, a3);
    a1 = fmaxf(a1, a2);
    a0 = fmaxf(a0, a1);

    // Warp suffix-inclusive scan of thread totals.
    // shfl_down past lane 31 returns own value == identity for max.
    float s = a0;
    #pragma unroll
    for (int off = 1; off < 32; off <<= 1) {
        float o = __shfl_down_sync(0xffffffffu, s, off);
        s = fmaxf(s, o);
    }
    // Carry from later threads in this warp = scan value at lane+1.
    float c = __shfl_down_sync(0xffffffffu, s, 1);
    if (lane == 31) c = -INFINITY;

    // Publish warp total (scan value at lane 0).
    if (lane == 0) tot[wid] = s;

    // Hoist store base off the post-barrier critical path.
    // Output: (final, final_2) concatenated, each (32,1024) row-major.
    // Thread t writes float4 indices 2t, 2t+1 of its output row.
    float4* o_out = (float4*)(out + ch * (B * T) + b * T) + 2 * t;

    __syncthreads();

    // Predicate-free carry from later warps: 3 pipelined broadcast LDS loads
    // (padding supplies -INF past warp 3), then a 2-level tree max.
    {
        float x1 = tot[wid + 1], x2 = tot[wid + 2], x3 = tot[wid + 3];
        c = fmaxf(c, fmaxf(fmaxf(x1, x2), x3));
    }

    float4 o4a, o4b;
    o4a.x = fmaxf(a0, c);
    o4a.y = fmaxf(a1, c);
    o4a.z = fmaxf(a2, c);
    o4a.w = fmaxf(a3, c);
    o4b.x = fmaxf(a4, c);
    o4b.y = fmaxf(a5, c);
    o4b.z = fmaxf(a6, c);
    o4b.w = fmaxf(a7, c);
    o_out[0] = o4a;
    o_out[1] = o4b;
}

extern "C" void kernel_launch(void* const* d_in, const int* in_sizes, int n_in,
                              void* d_out, int out_size) {
    const float4* signal = (const float4*)d_in[0];
    float* out = (float*)d_out;
    dim3 grid(B, 2);
    suffix_robustness_kernel<<<grid, THREADS>>>(signal, out);
}

// round 12
// speedup vs baseline: 1.4570x; 1.0108x over previous
#include <cuda_runtime.h>
#include <math.h>

// signal (32, 1024, 2) f32 interleaved. Per (batch, channel):
//   anded[t] = -|s| - log1p(exp(-2e5|s|))/1e5
//   out[t]   = suffix max of anded  (EV_SCALE=1e9 maxish == hard max to ~1e-9)
//
// grid=64: one CTA per (batch, channel). 128 threads, 8 timesteps/thread
// (4x LDG.128 issued in REVERSE so the suffix chain's first operand lands
// first), 4 warps. Single-channel scan chain, 4-warp barrier, 3-load
// predicate-free padded smem carry. Warp-uniform MUFU fast path (corr==0
// exactly when |c| > 4.37e-4, expf underflow).

static constexpr int T = 1024;
static constexpr int B = 32;
static constexpr int THREADS = 128;
static constexpr int NWARP = THREADS / 32;   // 4

__device__ __forceinline__ float corr_of(float a) {
    return __logf(1.0f + __expf(-200000.0f * a)) * 1e-5f;
}

__global__ __launch_bounds__(THREADS)
void suffix_robustness_kernel(const float4* __restrict__ signal,
                              float* __restrict__ out) {
    __shared__ float tot[2 * NWARP];

    const int b    = blockIdx.x;         // batch
    const int ch   = blockIdx.y;         // channel 0/1
    const int t    = threadIdx.x;        // thread handles timesteps 8t..8t+7
    const int lane = t & 31;
    const int wid  = t >> 5;

    // Pad totals [NWARP, 2*NWARP) with -INF (covered by the barrier below).
    if (t >= NWARP && t < 2 * NWARP) tot[t] = -INFINITY;

    // signal row b: 2048 floats = 512 float4. Each float4 = 2 timesteps of
    // both channels. Thread t reads float4 indices 4t..4t+3 (ts 8t..8t+7).
    // Issue in reverse: the suffix chain consumes p3's values first.
    const float4* row = signal + b * (T * 2 / 4) + 4 * t;
    float4 p3 = row[3];
    float4 p2 = row[2];
    float4 p1 = row[1];
    float4 p0 = row[0];

    float a7 = fabsf(ch ? p3.w : p3.z);
    float a6 = fabsf(ch ? p3.y : p3.x);
    float a5 = fabsf(ch ? p2.w : p2.z);
    float a4 = fabsf(ch ? p2.y : p2.x);
    float a3 = fabsf(ch ? p1.w : p1.z);
    float a2 = fabsf(ch ? p1.y : p1.x);
    float a1 = fabsf(ch ? p0.w : p0.z);
    float a0 = fabsf(ch ? p0.y : p0.x);

    float amin = fminf(fminf(fminf(a0, a1), fminf(a2, a3)),
                       fminf(fminf(a4, a5), fminf(a6, a7)));

    // Common path: plain negation (valid for both branches' starting point).
    a0 = -a0;  a1 = -a1;  a2 = -a2;  a3 = -a3;
    a4 = -a4;  a5 = -a5;  a6 = -a6;  a7 = -a7;

    // Rare path: subtract correction (corr(|c|)==0 exactly when |c|>4.37e-4).
    if (__ballot_sync(0xffffffffu, amin < 4.5e-4f)) {
        a0 -= corr_of(-a0);  a1 -= corr_of(-a1);
        a2 -= corr_of(-a2);  a3 -= corr_of(-a3);
        a4 -= corr_of(-a4);  a5 -= corr_of(-a5);
        a6 -= corr_of(-a6);  a7 -= corr_of(-a7);
    }

    // Per-thread suffix max: a_i = max(a_i .. a_7)
    a6 = fmaxf(a6, a7);
    a5 = fmaxf(a5, a6);
    a4 = fmaxf(a4, a5);
    a3 = fmaxf(a3, a4);
    a2 = fmaxf(a2, a3);
    a1 = fmaxf(a1, a2);
    a0 = fmaxf(a0, a1);

    // Warp suffix-inclusive scan of thread totals.
    // shfl_down past lane 31 returns own value == identity for max.
    float s = a0;
    #pragma unroll
    for (int off = 1; off < 32; off <<= 1) {
        float o = __shfl_down_sync(0xffffffffu, s, off);
        s = fmaxf(s, o);
    }
    // Carry from later threads in this warp = scan value at lane+1.
    float c = __shfl_down_sync(0xffffffffu, s, 1);
    if (lane == 31) c = -INFINITY;

    // Publish warp total (scan value at lane 0).
    if (lane == 0) tot[wid] = s;

    // Hoist store base off the post-barrier critical path.
    // Output: (final, final_2) concatenated, each (32,1024) row-major.
    float4* o_out = (float4*)(out + ch * (B * T) + b * T) + 2 * t;

    __syncthreads();

    // Predicate-free carry from later warps: 3 pipelined broadcast LDS loads
    // (padding supplies -INF past warp 3), then a 2-level tree max.
    {
        float x1 = tot[wid + 1], x2 = tot[wid + 2], x3 = tot[wid + 3];
        c = fmaxf(c, fmaxf(fmaxf(x1, x2), x3));
    }

    float4 o4a, o4b;
    o4a.x = fmaxf(a0, c);
    o4a.y = fmaxf(a1, c);
    o4a.z = fmaxf(a2, c);
    o4a.w = fmaxf(a3, c);
    o4b.x = fmaxf(a4, c);
    o4b.y = fmaxf(a5, c);
    o4b.z = fmaxf(a6, c);
    o4b.w = fmaxf(a7, c);
    o_out[0] = o4a;
    o_out[1] = o4b;
}

extern "C" void kernel_launch(void* const* d_in, const int* in_sizes, int n_in,
                              void* d_out, int out_size) {
    const float4* signal = (const float4*)d_in[0];
    float* out = (float*)d_out;
    dim3 grid(B, 2);
    suffix_robustness_kernel<<<grid, THREADS>>>(signal, out);
}